// round 1
// baseline (speedup 1.0000x reference)
#include <cuda_runtime.h>
#include <math.h>

#define DIM    1024
#define NHEADS 16
#define HDIM   64
#define BATCH  2
#define SEQ    2048
#define MTOT   (BATCH * SEQ)   // 4096

// ---------------- scratch (static device globals; no allocation) ----------------
__device__ float g_Q[MTOT * DIM];
__device__ float g_K[MTOT * DIM];
__device__ float g_V[MTOT * DIM];
__device__ float g_O[MTOT * DIM];

// ============================================================================
// Generic fp32 GEMM:  C[M,N] = A[M,K] * B[N,K]^T (+ bias[n])
// M=4096, N=1024, K=1024 fixed. BM=BN=128, BK=16, 256 threads, 8x8/thread.
// Columns per thread are strided by 16 -> conflict-free Bs loads.
// ============================================================================
__device__ __forceinline__ void gemm_body(
    const float* __restrict__ A,
    const float* __restrict__ B,
    const float* __restrict__ bias,
    float* __restrict__ C)
{
    constexpr int N = DIM;
    constexpr int K = DIM;

    __shared__ float As[16][132];   // [k][m], padded
    __shared__ float Bs[16][132];   // [k][n], padded

    const int tid = threadIdx.x;
    const int tr  = tid >> 4;       // 0..15 -> rows tr*8 .. tr*8+7
    const int tc  = tid & 15;       // 0..15 -> cols tc + j*16
    const int bm  = blockIdx.y * 128;
    const int bn  = blockIdx.x * 128;

    const int lrow  = tid >> 2;         // 0..63
    const int lcol  = (tid & 3) << 2;   // 0,4,8,12

    const float* Aptr = A + (size_t)(bm + lrow) * K + lcol;
    const float* Bptr = B + (size_t)(bn + lrow) * K + lcol;

    float acc[8][8];
#pragma unroll
    for (int i = 0; i < 8; i++)
#pragma unroll
        for (int j = 0; j < 8; j++) acc[i][j] = 0.0f;

    for (int k0 = 0; k0 < K; k0 += 16) {
#pragma unroll
        for (int r = 0; r < 128; r += 64) {
            float4 va = *(const float4*)(Aptr + (size_t)r * K + k0);
            As[lcol + 0][lrow + r] = va.x;
            As[lcol + 1][lrow + r] = va.y;
            As[lcol + 2][lrow + r] = va.z;
            As[lcol + 3][lrow + r] = va.w;
            float4 vb = *(const float4*)(Bptr + (size_t)r * K + k0);
            Bs[lcol + 0][lrow + r] = vb.x;
            Bs[lcol + 1][lrow + r] = vb.y;
            Bs[lcol + 2][lrow + r] = vb.z;
            Bs[lcol + 3][lrow + r] = vb.w;
        }
        __syncthreads();

#pragma unroll
        for (int kk = 0; kk < 16; kk++) {
            float a[8], b[8];
#pragma unroll
            for (int i = 0; i < 8; i++) a[i] = As[kk][tr * 8 + i];
#pragma unroll
            for (int j = 0; j < 8; j++) b[j] = Bs[kk][tc + j * 16];
#pragma unroll
            for (int i = 0; i < 8; i++)
#pragma unroll
                for (int j = 0; j < 8; j++)
                    acc[i][j] = fmaf(a[i], b[j], acc[i][j]);
        }
        __syncthreads();
    }

#pragma unroll
    for (int i = 0; i < 8; i++) {
        const size_t row = (size_t)(bm + tr * 8 + i);
#pragma unroll
        for (int j = 0; j < 8; j++) {
            const int col = bn + tc + j * 16;
            float v = acc[i][j];
            if (bias) v += bias[col];
            C[row * N + col] = v;
        }
    }
}

__global__ void __launch_bounds__(256, 2) gemm_qkv_kernel(
    const float* __restrict__ X,
    const float* __restrict__ Wq,
    const float* __restrict__ Wk,
    const float* __restrict__ Wv)
{
    const float* W;
    float* C;
    if (blockIdx.z == 0)      { W = Wq; C = g_Q; }
    else if (blockIdx.z == 1) { W = Wk; C = g_K; }
    else                      { W = Wv; C = g_V; }
    gemm_body(X, W, nullptr, C);
}

__global__ void __launch_bounds__(256, 2) gemm_out_kernel(
    const float* __restrict__ Wo,
    const float* __restrict__ bo,
    float* __restrict__ out)
{
    gemm_body(g_O, Wo, bo, out);
}

// ============================================================================
// Flash attention (fp32, causal). One block = 64 query rows of one (b,h).
// 256 threads; thread (tr,tc) owns rows tr*4+i, cols/d tc+j*16.
// Online softmax with half-warp shuffle reductions.
// ============================================================================
#define APAD 68
#define ATT_SMEM_FLOATS (4 * 64 * APAD + 128)
#define ATT_SMEM_BYTES  (ATT_SMEM_FLOATS * 4)

__global__ void __launch_bounds__(256, 2) attn_kernel()
{
    extern __shared__ float smem[];
    float (*Qs)[APAD] = (float(*)[APAD])(smem);
    float (*Ks)[APAD] = (float(*)[APAD])(smem + 64 * APAD);
    float (*Vs)[APAD] = (float(*)[APAD])(smem + 2 * 64 * APAD);
    float (*Ps)[APAD] = (float(*)[APAD])(smem + 3 * 64 * APAD);
    float* m_run = smem + 4 * 64 * APAD;        // [64]
    float* l_run = m_run + 64;                  // [64]

    const int qb = blockIdx.x;           // 0..31
    const int h  = blockIdx.y;           // 0..15
    const int b  = blockIdx.z;           // 0..1
    const int q0 = qb * 64;
    const float scale = 0.125f;          // 1/sqrt(64)

    const int tid = threadIdx.x;
    const int tr  = tid >> 4;            // 0..15
    const int tc  = tid & 15;            // 0..15

    const size_t head_off = (size_t)b * SEQ * DIM + (size_t)h * HDIM;

    // load + scale Q tile [64 x 64]
    {
        const int row = tid >> 4;         // 0..15
        const int f4  = (tid & 15) * 4;   // 0..60
#pragma unroll
        for (int r = 0; r < 64; r += 16) {
            float4 v = *(const float4*)(g_Q + head_off + (size_t)(q0 + row + r) * DIM + f4);
            v.x *= scale; v.y *= scale; v.z *= scale; v.w *= scale;
            *(float4*)&Qs[row + r][f4] = v;
        }
    }
    if (tid < 64) { m_run[tid] = -INFINITY; l_run[tid] = 0.0f; }

    float o_acc[4][4];
#pragma unroll
    for (int i = 0; i < 4; i++)
#pragma unroll
        for (int j = 0; j < 4; j++) o_acc[i][j] = 0.0f;

    for (int kb = 0; kb <= qb; kb++) {
        const int k0 = kb * 64;
        __syncthreads();   // protect Ks/Vs/Ps from previous iteration's readers

        // load K, V tiles
        {
            const int row = tid >> 4;
            const int f4  = (tid & 15) * 4;
#pragma unroll
            for (int r = 0; r < 64; r += 16) {
                *(float4*)&Ks[row + r][f4] =
                    *(const float4*)(g_K + head_off + (size_t)(k0 + row + r) * DIM + f4);
                *(float4*)&Vs[row + r][f4] =
                    *(const float4*)(g_V + head_off + (size_t)(k0 + row + r) * DIM + f4);
            }
        }
        __syncthreads();

        // S = Qs * Ks^T  (thread tile: rows tr*4+i, cols tc+j*16)
        float s[4][4];
#pragma unroll
        for (int i = 0; i < 4; i++)
#pragma unroll
            for (int j = 0; j < 4; j++) s[i][j] = 0.0f;

#pragma unroll 8
        for (int d = 0; d < 64; d++) {
            float a[4], bb[4];
#pragma unroll
            for (int i = 0; i < 4; i++) a[i] = Qs[tr * 4 + i][d];
#pragma unroll
            for (int j = 0; j < 4; j++) bb[j] = Ks[tc + j * 16][d];
#pragma unroll
            for (int i = 0; i < 4; i++)
#pragma unroll
                for (int j = 0; j < 4; j++)
                    s[i][j] = fmaf(a[i], bb[j], s[i][j]);
        }

        const bool diag = (kb == qb);

#pragma unroll
        for (int i = 0; i < 4; i++) {
            const int row  = tr * 4 + i;
            const int qpos = q0 + row;
            if (diag) {
#pragma unroll
                for (int j = 0; j < 4; j++) {
                    const int kpos = k0 + tc + j * 16;
                    if (kpos > qpos) s[i][j] = -INFINITY;
                }
            }
            float mx = fmaxf(fmaxf(s[i][0], s[i][1]), fmaxf(s[i][2], s[i][3]));
#pragma unroll
            for (int off = 8; off > 0; off >>= 1)
                mx = fmaxf(mx, __shfl_xor_sync(0xffffffffu, mx, off));

            const float mold = m_run[row];
            const float mnew = fmaxf(mold, mx);
            const float alpha = __expf(mold - mnew);

            float psum = 0.0f;
#pragma unroll
            for (int j = 0; j < 4; j++) {
                float p = __expf(s[i][j] - mnew);   // exp(-inf)=0 for masked
                s[i][j] = p;
                psum += p;
            }
#pragma unroll
            for (int off = 8; off > 0; off >>= 1)
                psum += __shfl_xor_sync(0xffffffffu, psum, off);

            if (tc == 0) {
                m_run[row] = mnew;
                l_run[row] = l_run[row] * alpha + psum;
            }
#pragma unroll
            for (int j = 0; j < 4; j++) {
                Ps[row][tc + j * 16] = s[i][j];
                o_acc[i][j] *= alpha;
            }
        }
        __syncthreads();

        // O += P * V
#pragma unroll 8
        for (int c = 0; c < 64; c++) {
            float a[4], bb[4];
#pragma unroll
            for (int i = 0; i < 4; i++) a[i] = Ps[tr * 4 + i][c];
#pragma unroll
            for (int j = 0; j < 4; j++) bb[j] = Vs[c][tc + j * 16];
#pragma unroll
            for (int i = 0; i < 4; i++)
#pragma unroll
                for (int j = 0; j < 4; j++)
                    o_acc[i][j] = fmaf(a[i], bb[j], o_acc[i][j]);
        }
    }

    __syncthreads();
#pragma unroll
    for (int i = 0; i < 4; i++) {
        const int row = tr * 4 + i;
        const float inv = 1.0f / l_run[row];
#pragma unroll
        for (int j = 0; j < 4; j++) {
            g_O[head_off + (size_t)(q0 + row) * DIM + tc + j * 16] = o_acc[i][j] * inv;
        }
    }
}

// ============================================================================
// launch
// ============================================================================
extern "C" void kernel_launch(void* const* d_in, const int* in_sizes, int n_in,
                              void* d_out, int out_size)
{
    const float* x  = (const float*)d_in[0];
    const float* Wq = (const float*)d_in[1];
    const float* Wk = (const float*)d_in[2];
    const float* Wv = (const float*)d_in[3];
    const float* Wo = (const float*)d_in[4];
    const float* bo = (const float*)d_in[5];
    float* out = (float*)d_out;

    // QKV projections: one launch, z selects weight/output
    dim3 gridQKV(DIM / 128, MTOT / 128, 3);
    gemm_qkv_kernel<<<gridQKV, 256>>>(x, Wq, Wk, Wv);

    // flash attention
    cudaFuncSetAttribute(attn_kernel,
                         cudaFuncAttributeMaxDynamicSharedMemorySize,
                         ATT_SMEM_BYTES);
    dim3 gridAtt(SEQ / 64, NHEADS, BATCH);
    attn_kernel<<<gridAtt, 256, ATT_SMEM_BYTES>>>();

    // output projection + bias
    dim3 gridOut(DIM / 128, MTOT / 128);
    gemm_out_kernel<<<gridOut, 256>>>(Wo, bo, out);
}

// round 2
// speedup vs baseline: 1.6789x; 1.6789x over previous
#include <cuda_runtime.h>
#include <cuda_bf16.h>
#include <math.h>
#include <stdint.h>

#define DIM    1024
#define NHEADS 16
#define HDIM   64
#define BATCH  2
#define SEQ    2048
#define MTOT   (BATCH * SEQ)   // 4096

// ---------------- scratch (static device globals; no allocation) ----------------
__device__ float g_Q[MTOT * DIM];
__device__ float g_K[MTOT * DIM];
__device__ float g_V[MTOT * DIM];
__device__ float g_O[MTOT * DIM];

// bf16 split copies (hi/lo) for tensor-core GEMMs
__device__ unsigned short g_x_hi[MTOT * DIM];
__device__ unsigned short g_x_lo[MTOT * DIM];
__device__ unsigned short g_w_hi[4 * DIM * DIM];   // Wq, Wk, Wv, Wo
__device__ unsigned short g_w_lo[4 * DIM * DIM];
__device__ unsigned short g_o_hi[MTOT * DIM];
__device__ unsigned short g_o_lo[MTOT * DIM];

// ============================================================================
// fp32 -> bf16 hi/lo split kernels
// ============================================================================
__device__ __forceinline__ void split1(float v, unsigned short& h, unsigned short& l)
{
    __nv_bfloat16 hb = __float2bfloat16(v);
    h = __bfloat16_as_ushort(hb);
    l = __bfloat16_as_ushort(__float2bfloat16(v - __bfloat162float(hb)));
}

__device__ __forceinline__ void split4(const float4 v, ushort4& h, ushort4& l)
{
    split1(v.x, h.x, l.x);
    split1(v.y, h.y, l.y);
    split1(v.z, h.z, l.z);
    split1(v.w, h.w, l.w);
}

__global__ void split_x_kernel(const float* __restrict__ src)
{
    int i = blockIdx.x * 256 + threadIdx.x;          // over MTOT*DIM/4
    float4 v = ((const float4*)src)[i];
    ushort4 h, l;
    split4(v, h, l);
    ((ushort4*)g_x_hi)[i] = h;
    ((ushort4*)g_x_lo)[i] = l;
}

__global__ void split_w_kernel(const float* __restrict__ w, int z)
{
    int i = blockIdx.x * 256 + threadIdx.x;          // over DIM*DIM/4
    float4 v = ((const float4*)w)[i];
    ushort4 h, l;
    split4(v, h, l);
    size_t base = (size_t)z * (DIM * DIM / 4);
    ((ushort4*)g_w_hi)[base + i] = h;
    ((ushort4*)g_w_lo)[base + i] = l;
}

__global__ void split_o_kernel()
{
    int i = blockIdx.x * 256 + threadIdx.x;          // over MTOT*DIM/4
    float4 v = ((const float4*)g_O)[i];
    ushort4 h, l;
    split4(v, h, l);
    ((ushort4*)g_o_hi)[i] = h;
    ((ushort4*)g_o_lo)[i] = l;
}

// ============================================================================
// bf16x3 tensor-core GEMM:  C[M,N] = A[M,K] * B[N,K]^T (+ bias)
// BM=128, BN=64, BK=64, 256 threads (8 warps: 4m x 2n), 2-stage cp.async.
// smem: per stage Ah(16K)+Al(16K)+Bh(8K)+Bl(8K) = 48KB; x2 stages = 96KB.
// ============================================================================
#define STG_BYTES 49152
#define AH_OFF 0
#define AL_OFF 16384
#define BH_OFF 32768
#define BL_OFF 40960
#define GEMM_SMEM (2 * STG_BYTES)

__device__ __forceinline__ void cp16(uint32_t dst, const void* src)
{
    asm volatile("cp.async.cg.shared.global [%0], [%1], 16;\n" :: "r"(dst), "l"(src));
}
__device__ __forceinline__ void cp_commit()
{
    asm volatile("cp.async.commit_group;\n");
}
template<int N> __device__ __forceinline__ void cp_wait()
{
    asm volatile("cp.async.wait_group %0;\n" :: "n"(N));
}
__device__ __forceinline__ void ldsm_x4(uint32_t* r, uint32_t addr)
{
    asm volatile("ldmatrix.sync.aligned.m8n8.x4.shared.b16 {%0,%1,%2,%3}, [%4];"
                 : "=r"(r[0]), "=r"(r[1]), "=r"(r[2]), "=r"(r[3]) : "r"(addr));
}
__device__ __forceinline__ void mma_bf16(float* c, const uint32_t* a, const uint32_t* b)
{
    asm volatile("mma.sync.aligned.m16n8k16.row.col.f32.bf16.bf16.f32 "
                 "{%0,%1,%2,%3},{%4,%5,%6,%7},{%8,%9},{%0,%1,%2,%3};"
                 : "+f"(c[0]), "+f"(c[1]), "+f"(c[2]), "+f"(c[3])
                 : "r"(a[0]), "r"(a[1]), "r"(a[2]), "r"(a[3]), "r"(b[0]), "r"(b[1]));
}

__device__ __forceinline__ void gemm_bf16_body(
    const unsigned short* __restrict__ Ah, const unsigned short* __restrict__ Al,
    const unsigned short* __restrict__ Bh, const unsigned short* __restrict__ Bl,
    const float* __restrict__ bias, float* __restrict__ C)
{
    extern __shared__ char dsm[];
    const uint32_t sbase = (uint32_t)__cvta_generic_to_shared(dsm);

    const int tid  = threadIdx.x;
    const int bm   = blockIdx.y * 128;
    const int bn   = blockIdx.x * 64;
    const int lane = tid & 31;
    const int warp = tid >> 5;
    const int wm   = warp & 3;      // 0..3 -> 32 rows each
    const int wn   = warp >> 2;     // 0..1 -> 32 cols each

    // loader: A tile 128x64 bf16 (1024 16B-chunks), B tile 64x64 (512 chunks)
    auto load_stage = [&](int s, int k0) {
        const uint32_t sb = sbase + s * STG_BYTES;
#pragma unroll
        for (int t = 0; t < 4; t++) {
            int c   = tid + t * 256;
            int row = c >> 3, ch = c & 7;
            size_t   gofs = (size_t)(bm + row) * DIM + k0 + ch * 8;
            uint32_t sofs = row * 128 + ((ch ^ (row & 7)) << 4);
            cp16(sb + AH_OFF + sofs, Ah + gofs);
            cp16(sb + AL_OFF + sofs, Al + gofs);
        }
#pragma unroll
        for (int t = 0; t < 2; t++) {
            int c   = tid + t * 256;
            int row = c >> 3, ch = c & 7;
            size_t   gofs = (size_t)(bn + row) * DIM + k0 + ch * 8;
            uint32_t sofs = row * 128 + ((ch ^ (row & 7)) << 4);
            cp16(sb + BH_OFF + sofs, Bh + gofs);
            cp16(sb + BL_OFF + sofs, Bl + gofs);
        }
    };

    float acc[2][4][4];
#pragma unroll
    for (int i = 0; i < 2; i++)
#pragma unroll
        for (int j = 0; j < 4; j++)
#pragma unroll
            for (int k = 0; k < 4; k++) acc[i][j][k] = 0.0f;

    // ldmatrix address components
    const int a_r = wm * 32 + (lane & 15);          // row within A tile (+ mf*16)
    const int a_k = (lane >> 4);                    // k half (0/1)
    const int a_x = a_r & 7;
    const int b_r = wn * 32 + (lane & 7) + ((lane >> 4) << 3);  // row within B tile (+ nf2*16)
    const int b_k = (lane >> 3) & 1;
    const int b_x = lane & 7;

    load_stage(0, 0);
    cp_commit();

    constexpr int NIT = DIM / 64;   // 16
    for (int it = 0; it < NIT; ++it) {
        const int s = it & 1;
        if (it + 1 < NIT) {
            load_stage(s ^ 1, (it + 1) * 64);
            cp_commit();
            cp_wait<1>();
        } else {
            cp_wait<0>();
        }
        __syncthreads();

        const uint32_t sb = sbase + s * STG_BYTES;
#pragma unroll
        for (int ks = 0; ks < 4; ks++) {
            uint32_t ah[2][4], al[2][4], bh[2][4], bl[2][4];
#pragma unroll
            for (int mf = 0; mf < 2; mf++) {
                uint32_t off = (a_r + mf * 16) * 128 + ((((ks << 1) | a_k) ^ a_x) << 4);
                ldsm_x4(ah[mf], sb + AH_OFF + off);
                ldsm_x4(al[mf], sb + AL_OFF + off);
            }
#pragma unroll
            for (int nf2 = 0; nf2 < 2; nf2++) {
                uint32_t off = (b_r + nf2 * 16) * 128 + ((((ks << 1) | b_k) ^ b_x) << 4);
                ldsm_x4(bh[nf2], sb + BH_OFF + off);
                ldsm_x4(bl[nf2], sb + BL_OFF + off);
            }
#pragma unroll
            for (int mf = 0; mf < 2; mf++)
#pragma unroll
                for (int nf = 0; nf < 4; nf++) {
                    const uint32_t* bhp = &bh[nf >> 1][(nf & 1) * 2];
                    const uint32_t* blp = &bl[nf >> 1][(nf & 1) * 2];
                    mma_bf16(acc[mf][nf], ah[mf], bhp);
                    mma_bf16(acc[mf][nf], al[mf], bhp);
                    mma_bf16(acc[mf][nf], ah[mf], blp);
                }
        }
        __syncthreads();
    }

    // epilogue
#pragma unroll
    for (int mf = 0; mf < 2; mf++) {
        const int row0 = bm + wm * 32 + mf * 16 + (lane >> 2);
#pragma unroll
        for (int nf = 0; nf < 4; nf++) {
            const int col = bn + wn * 32 + nf * 8 + (lane & 3) * 2;
            float b0 = 0.f, b1 = 0.f;
            if (bias) { b0 = bias[col]; b1 = bias[col + 1]; }
            float2 v0 = make_float2(acc[mf][nf][0] + b0, acc[mf][nf][1] + b1);
            float2 v1 = make_float2(acc[mf][nf][2] + b0, acc[mf][nf][3] + b1);
            *(float2*)(C + (size_t)row0 * DIM + col)       = v0;
            *(float2*)(C + (size_t)(row0 + 8) * DIM + col) = v1;
        }
    }
}

__global__ void __launch_bounds__(256, 2) gemm_qkv_bf16()
{
    const int z = blockIdx.z;
    float* C = (z == 0) ? g_Q : (z == 1) ? g_K : g_V;
    gemm_bf16_body(g_x_hi, g_x_lo,
                   g_w_hi + (size_t)z * DIM * DIM, g_w_lo + (size_t)z * DIM * DIM,
                   nullptr, C);
}

__global__ void __launch_bounds__(256, 2) gemm_out_bf16(
    const float* __restrict__ bo, float* __restrict__ out)
{
    gemm_bf16_body(g_o_hi, g_o_lo,
                   g_w_hi + (size_t)3 * DIM * DIM, g_w_lo + (size_t)3 * DIM * DIM,
                   bo, out);
}

// ============================================================================
// Flash attention (fp32, causal). One block = 64 query rows of one (b,h).
// ============================================================================
#define APAD 68
#define ATT_SMEM_FLOATS (4 * 64 * APAD + 128)
#define ATT_SMEM_BYTES  (ATT_SMEM_FLOATS * 4)

__global__ void __launch_bounds__(256, 2) attn_kernel()
{
    extern __shared__ float smem[];
    float (*Qs)[APAD] = (float(*)[APAD])(smem);
    float (*Ks)[APAD] = (float(*)[APAD])(smem + 64 * APAD);
    float (*Vs)[APAD] = (float(*)[APAD])(smem + 2 * 64 * APAD);
    float (*Ps)[APAD] = (float(*)[APAD])(smem + 3 * 64 * APAD);
    float* m_run = smem + 4 * 64 * APAD;        // [64]
    float* l_run = m_run + 64;                  // [64]

    const int qb = blockIdx.x;
    const int h  = blockIdx.y;
    const int b  = blockIdx.z;
    const int q0 = qb * 64;
    const float scale = 0.125f;

    const int tid = threadIdx.x;
    const int tr  = tid >> 4;
    const int tc  = tid & 15;

    const size_t head_off = (size_t)b * SEQ * DIM + (size_t)h * HDIM;

    {
        const int row = tid >> 4;
        const int f4  = (tid & 15) * 4;
#pragma unroll
        for (int r = 0; r < 64; r += 16) {
            float4 v = *(const float4*)(g_Q + head_off + (size_t)(q0 + row + r) * DIM + f4);
            v.x *= scale; v.y *= scale; v.z *= scale; v.w *= scale;
            *(float4*)&Qs[row + r][f4] = v;
        }
    }
    if (tid < 64) { m_run[tid] = -INFINITY; l_run[tid] = 0.0f; }

    float o_acc[4][4];
#pragma unroll
    for (int i = 0; i < 4; i++)
#pragma unroll
        for (int j = 0; j < 4; j++) o_acc[i][j] = 0.0f;

    for (int kb = 0; kb <= qb; kb++) {
        const int k0 = kb * 64;
        __syncthreads();

        {
            const int row = tid >> 4;
            const int f4  = (tid & 15) * 4;
#pragma unroll
            for (int r = 0; r < 64; r += 16) {
                *(float4*)&Ks[row + r][f4] =
                    *(const float4*)(g_K + head_off + (size_t)(k0 + row + r) * DIM + f4);
                *(float4*)&Vs[row + r][f4] =
                    *(const float4*)(g_V + head_off + (size_t)(k0 + row + r) * DIM + f4);
            }
        }
        __syncthreads();

        float s[4][4];
#pragma unroll
        for (int i = 0; i < 4; i++)
#pragma unroll
            for (int j = 0; j < 4; j++) s[i][j] = 0.0f;

#pragma unroll 8
        for (int d = 0; d < 64; d++) {
            float a[4], bb[4];
#pragma unroll
            for (int i = 0; i < 4; i++) a[i] = Qs[tr * 4 + i][d];
#pragma unroll
            for (int j = 0; j < 4; j++) bb[j] = Ks[tc + j * 16][d];
#pragma unroll
            for (int i = 0; i < 4; i++)
#pragma unroll
                for (int j = 0; j < 4; j++)
                    s[i][j] = fmaf(a[i], bb[j], s[i][j]);
        }

        const bool diag = (kb == qb);

#pragma unroll
        for (int i = 0; i < 4; i++) {
            const int row  = tr * 4 + i;
            const int qpos = q0 + row;
            if (diag) {
#pragma unroll
                for (int j = 0; j < 4; j++) {
                    const int kpos = k0 + tc + j * 16;
                    if (kpos > qpos) s[i][j] = -INFINITY;
                }
            }
            float mx = fmaxf(fmaxf(s[i][0], s[i][1]), fmaxf(s[i][2], s[i][3]));
#pragma unroll
            for (int off = 8; off > 0; off >>= 1)
                mx = fmaxf(mx, __shfl_xor_sync(0xffffffffu, mx, off));

            const float mold = m_run[row];
            const float mnew = fmaxf(mold, mx);
            const float alpha = __expf(mold - mnew);

            float psum = 0.0f;
#pragma unroll
            for (int j = 0; j < 4; j++) {
                float p = __expf(s[i][j] - mnew);
                s[i][j] = p;
                psum += p;
            }
#pragma unroll
            for (int off = 8; off > 0; off >>= 1)
                psum += __shfl_xor_sync(0xffffffffu, psum, off);

            if (tc == 0) {
                m_run[row] = mnew;
                l_run[row] = l_run[row] * alpha + psum;
            }
#pragma unroll
            for (int j = 0; j < 4; j++) {
                Ps[row][tc + j * 16] = s[i][j];
                o_acc[i][j] *= alpha;
            }
        }
        __syncthreads();

#pragma unroll 8
        for (int c = 0; c < 64; c++) {
            float a[4], bb[4];
#pragma unroll
            for (int i = 0; i < 4; i++) a[i] = Ps[tr * 4 + i][c];
#pragma unroll
            for (int j = 0; j < 4; j++) bb[j] = Vs[c][tc + j * 16];
#pragma unroll
            for (int i = 0; i < 4; i++)
#pragma unroll
                for (int j = 0; j < 4; j++)
                    o_acc[i][j] = fmaf(a[i], bb[j], o_acc[i][j]);
        }
    }

    __syncthreads();
#pragma unroll
    for (int i = 0; i < 4; i++) {
        const int row = tr * 4 + i;
        const float inv = 1.0f / l_run[row];
#pragma unroll
        for (int j = 0; j < 4; j++) {
            g_O[head_off + (size_t)(q0 + row) * DIM + tc + j * 16] = o_acc[i][j] * inv;
        }
    }
}

// ============================================================================
// launch
// ============================================================================
extern "C" void kernel_launch(void* const* d_in, const int* in_sizes, int n_in,
                              void* d_out, int out_size)
{
    const float* x  = (const float*)d_in[0];
    const float* Wq = (const float*)d_in[1];
    const float* Wk = (const float*)d_in[2];
    const float* Wv = (const float*)d_in[3];
    const float* Wo = (const float*)d_in[4];
    const float* bo = (const float*)d_in[5];
    float* out = (float*)d_out;

    cudaFuncSetAttribute(gemm_qkv_bf16, cudaFuncAttributeMaxDynamicSharedMemorySize, GEMM_SMEM);
    cudaFuncSetAttribute(gemm_out_bf16, cudaFuncAttributeMaxDynamicSharedMemorySize, GEMM_SMEM);
    cudaFuncSetAttribute(attn_kernel,   cudaFuncAttributeMaxDynamicSharedMemorySize, ATT_SMEM_BYTES);

    // bf16 hi/lo splits of x and weights
    split_x_kernel<<<MTOT * DIM / 4 / 256, 256>>>(x);
    split_w_kernel<<<DIM * DIM / 4 / 256, 256>>>(Wq, 0);
    split_w_kernel<<<DIM * DIM / 4 / 256, 256>>>(Wk, 1);
    split_w_kernel<<<DIM * DIM / 4 / 256, 256>>>(Wv, 2);
    split_w_kernel<<<DIM * DIM / 4 / 256, 256>>>(Wo, 3);

    // QKV projections (tensor core, bf16x3)
    dim3 gridQKV(DIM / 64, MTOT / 128, 3);
    gemm_qkv_bf16<<<gridQKV, 256, GEMM_SMEM>>>();

    // flash attention (fp32)
    dim3 gridAtt(SEQ / 64, NHEADS, BATCH);
    attn_kernel<<<gridAtt, 256, ATT_SMEM_BYTES>>>();

    // split attention output, then output projection (tensor core, bf16x3)
    split_o_kernel<<<MTOT * DIM / 4 / 256, 256>>>();
    dim3 gridOut(DIM / 64, MTOT / 128);
    gemm_out_bf16<<<gridOut, 256, GEMM_SMEM>>>(bo, out);
}

// round 3
// speedup vs baseline: 3.2860x; 1.9572x over previous
#include <cuda_runtime.h>
#include <cuda_bf16.h>
#include <math.h>
#include <stdint.h>

#define DIM    1024
#define NHEADS 16
#define HDIM   64
#define BATCH  2
#define SEQ    2048
#define MTOT   (BATCH * SEQ)   // 4096

// ---------------- scratch (static device globals; no allocation) ----------------
// bf16 split copies (hi/lo)
__device__ unsigned short g_x_hi[MTOT * DIM];
__device__ unsigned short g_x_lo[MTOT * DIM];
__device__ unsigned short g_w_hi[4 * DIM * DIM];   // Wq, Wk, Wv, Wo
__device__ unsigned short g_w_lo[4 * DIM * DIM];
// Q/K/V in head-major layout [B][H][T][D], bf16 hi/lo (Q pre-scaled by 1/8)
__device__ unsigned short g_q_hi[MTOT * DIM];
__device__ unsigned short g_q_lo[MTOT * DIM];
__device__ unsigned short g_k_hi[MTOT * DIM];
__device__ unsigned short g_k_lo[MTOT * DIM];
__device__ unsigned short g_v_hi[MTOT * DIM];
__device__ unsigned short g_v_lo[MTOT * DIM];
// attention output, token-major [MTOT][DIM], bf16 hi/lo
__device__ unsigned short g_o_hi[MTOT * DIM];
__device__ unsigned short g_o_lo[MTOT * DIM];

// ============================================================================
// helpers
// ============================================================================
__device__ __forceinline__ void split1(float v, unsigned short& h, unsigned short& l)
{
    __nv_bfloat16 hb = __float2bfloat16(v);
    h = __bfloat16_as_ushort(hb);
    l = __bfloat16_as_ushort(__float2bfloat16(v - __bfloat162float(hb)));
}
__device__ __forceinline__ void split4(const float4 v, ushort4& h, ushort4& l)
{
    split1(v.x, h.x, l.x);
    split1(v.y, h.y, l.y);
    split1(v.z, h.z, l.z);
    split1(v.w, h.w, l.w);
}
__device__ __forceinline__ uint32_t bf2pack(float a, float b)
{
    __nv_bfloat162 t = __floats2bfloat162_rn(a, b);
    return *reinterpret_cast<uint32_t*>(&t);
}
__device__ __forceinline__ float bfhi(float v)
{
    return __bfloat162float(__float2bfloat16(v));
}

__global__ void split_x_kernel(const float* __restrict__ src)
{
    int i = blockIdx.x * 256 + threadIdx.x;          // over MTOT*DIM/4
    float4 v = ((const float4*)src)[i];
    ushort4 h, l;
    split4(v, h, l);
    ((ushort4*)g_x_hi)[i] = h;
    ((ushort4*)g_x_lo)[i] = l;
}

__global__ void split_w_kernel(const float* __restrict__ w, int z)
{
    int i = blockIdx.x * 256 + threadIdx.x;          // over DIM*DIM/4
    float4 v = ((const float4*)w)[i];
    ushort4 h, l;
    split4(v, h, l);
    size_t base = (size_t)z * (DIM * DIM / 4);
    ((ushort4*)g_w_hi)[base + i] = h;
    ((ushort4*)g_w_lo)[base + i] = l;
}

// ============================================================================
// mma / ldmatrix / cp.async primitives
// ============================================================================
__device__ __forceinline__ void cp16(uint32_t dst, const void* src)
{
    asm volatile("cp.async.cg.shared.global [%0], [%1], 16;\n" :: "r"(dst), "l"(src));
}
__device__ __forceinline__ void cp_commit()
{
    asm volatile("cp.async.commit_group;\n");
}
template<int N> __device__ __forceinline__ void cp_wait()
{
    asm volatile("cp.async.wait_group %0;\n" :: "n"(N));
}
__device__ __forceinline__ void ldsm_x4(uint32_t* r, uint32_t addr)
{
    asm volatile("ldmatrix.sync.aligned.m8n8.x4.shared.b16 {%0,%1,%2,%3}, [%4];"
                 : "=r"(r[0]), "=r"(r[1]), "=r"(r[2]), "=r"(r[3]) : "r"(addr));
}
__device__ __forceinline__ void ldsm_x4_t(uint32_t* r, uint32_t addr)
{
    asm volatile("ldmatrix.sync.aligned.m8n8.x4.trans.shared.b16 {%0,%1,%2,%3}, [%4];"
                 : "=r"(r[0]), "=r"(r[1]), "=r"(r[2]), "=r"(r[3]) : "r"(addr));
}
__device__ __forceinline__ void mma_bf16(float* c, const uint32_t* a, const uint32_t* b)
{
    asm volatile("mma.sync.aligned.m16n8k16.row.col.f32.bf16.bf16.f32 "
                 "{%0,%1,%2,%3},{%4,%5,%6,%7},{%8,%9},{%0,%1,%2,%3};"
                 : "+f"(c[0]), "+f"(c[1]), "+f"(c[2]), "+f"(c[3])
                 : "r"(a[0]), "r"(a[1]), "r"(a[2]), "r"(a[3]), "r"(b[0]), "r"(b[1]));
}

// ============================================================================
// bf16x3 tensor-core GEMM:  C[M,N] = A[M,K] * B[N,K]^T
// BM=128, BN=64, BK=64, 256 threads (8 warps: 4m x 2n), 2-stage cp.async.
// MODE 0: write bf16 hi/lo split into head-major [B,H,T,D] layout, scaled.
// MODE 1: write fp32 + bias to C (token-major).
// ============================================================================
#define STG_BYTES 49152
#define AH_OFF 0
#define AL_OFF 16384
#define BH_OFF 32768
#define BL_OFF 40960
#define GEMM_SMEM (2 * STG_BYTES)

template<int MODE>
__device__ __forceinline__ void gemm_bf16_body(
    const unsigned short* __restrict__ Ah, const unsigned short* __restrict__ Al,
    const unsigned short* __restrict__ Bh, const unsigned short* __restrict__ Bl,
    float scale,
    unsigned short* __restrict__ Chi, unsigned short* __restrict__ Clo,
    const float* __restrict__ bias, float* __restrict__ C)
{
    extern __shared__ char dsm[];
    const uint32_t sbase = (uint32_t)__cvta_generic_to_shared(dsm);

    const int tid  = threadIdx.x;
    const int bm   = blockIdx.y * 128;
    const int bn   = blockIdx.x * 64;
    const int lane = tid & 31;
    const int warp = tid >> 5;
    const int wm   = warp & 3;
    const int wn   = warp >> 2;

    auto load_stage = [&](int s, int k0) {
        const uint32_t sb = sbase + s * STG_BYTES;
#pragma unroll
        for (int t = 0; t < 4; t++) {
            int c   = tid + t * 256;
            int row = c >> 3, ch = c & 7;
            size_t   gofs = (size_t)(bm + row) * DIM + k0 + ch * 8;
            uint32_t sofs = row * 128 + ((ch ^ (row & 7)) << 4);
            cp16(sb + AH_OFF + sofs, Ah + gofs);
            cp16(sb + AL_OFF + sofs, Al + gofs);
        }
#pragma unroll
        for (int t = 0; t < 2; t++) {
            int c   = tid + t * 256;
            int row = c >> 3, ch = c & 7;
            size_t   gofs = (size_t)(bn + row) * DIM + k0 + ch * 8;
            uint32_t sofs = row * 128 + ((ch ^ (row & 7)) << 4);
            cp16(sb + BH_OFF + sofs, Bh + gofs);
            cp16(sb + BL_OFF + sofs, Bl + gofs);
        }
    };

    float acc[2][4][4];
#pragma unroll
    for (int i = 0; i < 2; i++)
#pragma unroll
        for (int j = 0; j < 4; j++)
#pragma unroll
            for (int k = 0; k < 4; k++) acc[i][j][k] = 0.0f;

    const int a_r = wm * 32 + (lane & 15);
    const int a_k = (lane >> 4);
    const int a_x = a_r & 7;
    const int b_r = wn * 32 + (lane & 7) + ((lane >> 4) << 3);
    const int b_k = (lane >> 3) & 1;
    const int b_x = b_r & 7;

    load_stage(0, 0);
    cp_commit();

    constexpr int NIT = DIM / 64;   // 16
    for (int it = 0; it < NIT; ++it) {
        const int s = it & 1;
        if (it + 1 < NIT) {
            load_stage(s ^ 1, (it + 1) * 64);
            cp_commit();
            cp_wait<1>();
        } else {
            cp_wait<0>();
        }
        __syncthreads();

        const uint32_t sb = sbase + s * STG_BYTES;
#pragma unroll
        for (int ks = 0; ks < 4; ks++) {
            uint32_t ah[2][4], al[2][4], bh[2][4], bl[2][4];
#pragma unroll
            for (int mf = 0; mf < 2; mf++) {
                uint32_t off = (a_r + mf * 16) * 128 + ((((ks << 1) | a_k) ^ a_x) << 4);
                ldsm_x4(ah[mf], sb + AH_OFF + off);
                ldsm_x4(al[mf], sb + AL_OFF + off);
            }
#pragma unroll
            for (int nf2 = 0; nf2 < 2; nf2++) {
                uint32_t off = (b_r + nf2 * 16) * 128 + ((((ks << 1) | b_k) ^ b_x) << 4);
                ldsm_x4(bh[nf2], sb + BH_OFF + off);
                ldsm_x4(bl[nf2], sb + BL_OFF + off);
            }
#pragma unroll
            for (int mf = 0; mf < 2; mf++)
#pragma unroll
                for (int nf = 0; nf < 4; nf++) {
                    const uint32_t* bhp = &bh[nf >> 1][(nf & 1) * 2];
                    const uint32_t* blp = &bl[nf >> 1][(nf & 1) * 2];
                    mma_bf16(acc[mf][nf], ah[mf], bhp);
                    mma_bf16(acc[mf][nf], al[mf], bhp);
                    mma_bf16(acc[mf][nf], ah[mf], blp);
                }
        }
        __syncthreads();
    }

    // epilogue
#pragma unroll
    for (int mf = 0; mf < 2; mf++) {
        const int row0 = bm + wm * 32 + mf * 16 + (lane >> 2);
#pragma unroll
        for (int nf = 0; nf < 4; nf++) {
            const int col = bn + wn * 32 + nf * 8 + (lane & 3) * 2;
            if (MODE == 0) {
                // split + scatter to head-major [B,H,T,D]
                const int h = col >> 6, d = col & 63;
#pragma unroll
                for (int half = 0; half < 2; half++) {
                    const int row = row0 + half * 8;
                    const int b = row >> 11, t = row & 2047;
                    const size_t dst = (((size_t)(b * NHEADS + h) * SEQ) + t) * HDIM + d;
                    float f0 = acc[mf][nf][half * 2 + 0] * scale;
                    float f1 = acc[mf][nf][half * 2 + 1] * scale;
                    unsigned short h0, l0, h1, l1;
                    split1(f0, h0, l0);
                    split1(f1, h1, l1);
                    *(ushort2*)(Chi + dst) = make_ushort2(h0, h1);
                    *(ushort2*)(Clo + dst) = make_ushort2(l0, l1);
                }
            } else {
                float b0 = bias[col], b1 = bias[col + 1];
                float2 v0 = make_float2(acc[mf][nf][0] + b0, acc[mf][nf][1] + b1);
                float2 v1 = make_float2(acc[mf][nf][2] + b0, acc[mf][nf][3] + b1);
                *(float2*)(C + (size_t)row0 * DIM + col)       = v0;
                *(float2*)(C + (size_t)(row0 + 8) * DIM + col) = v1;
            }
        }
    }
}

__global__ void __launch_bounds__(256, 2) gemm_qkv_bf16()
{
    const int z = blockIdx.z;
    unsigned short* Chi = (z == 0) ? g_q_hi : (z == 1) ? g_k_hi : g_v_hi;
    unsigned short* Clo = (z == 0) ? g_q_lo : (z == 1) ? g_k_lo : g_v_lo;
    const float scale = (z == 0) ? 0.125f : 1.0f;
    gemm_bf16_body<0>(g_x_hi, g_x_lo,
                      g_w_hi + (size_t)z * DIM * DIM, g_w_lo + (size_t)z * DIM * DIM,
                      scale, Chi, Clo, nullptr, nullptr);
}

__global__ void __launch_bounds__(256, 2) gemm_out_bf16(
    const float* __restrict__ bo, float* __restrict__ out)
{
    gemm_bf16_body<1>(g_o_hi, g_o_lo,
                      g_w_hi + (size_t)3 * DIM * DIM, g_w_lo + (size_t)3 * DIM * DIM,
                      1.0f, nullptr, nullptr, bo, out);
}

// ============================================================================
// Tensor-core flash attention (bf16x3, causal).
// 256 threads (8 warps x 16 q-rows = BQ 128), BK=64, double-buffered K/V.
// ============================================================================
#define ATT_QH 0
#define ATT_QL 16384
#define ATT_STG0 32768
#define ATT_STG_BYTES 32768       // Kh 8K | Kl 8K | Vh 8K | Vl 8K
#define ATT_KH 0
#define ATT_KL 8192
#define ATT_VH 16384
#define ATT_VL 24576
#define ATT_SMEM (ATT_STG0 + 2 * ATT_STG_BYTES)   // 96KB

#define NEG_INF __int_as_float(0xff800000)

__global__ void __launch_bounds__(256, 1) attn_mma_kernel()
{
    extern __shared__ char dsm[];
    const uint32_t sbase = (uint32_t)__cvta_generic_to_shared(dsm);

    const int tid  = threadIdx.x;
    const int lane = tid & 31;
    const int w    = tid >> 5;           // 0..7
    const int qb   = (gridDim.x - 1) - blockIdx.x;   // big tiles first
    const int h    = blockIdx.y;
    const int b    = blockIdx.z;
    const int q0   = qb * 128;

    const size_t head = (size_t)(b * NHEADS + h) * SEQ * HDIM;
    const unsigned short* Qh = g_q_hi + head;
    const unsigned short* Ql = g_q_lo + head;
    const unsigned short* Kh = g_k_hi + head;
    const unsigned short* Kl = g_k_lo + head;
    const unsigned short* Vh = g_v_hi + head;
    const unsigned short* Vl = g_v_lo + head;

    // ---- load Q tile (128 rows x 64 bf16, hi+lo) ----
#pragma unroll
    for (int t = 0; t < 4; t++) {
        int c = tid + t * 256;           // 0..1023
        int row = c >> 3, ch = c & 7;
        size_t   g = (size_t)(q0 + row) * HDIM + ch * 8;
        uint32_t sofs = row * 128 + ((ch ^ (row & 7)) << 4);
        cp16(sbase + ATT_QH + sofs, Qh + g);
        cp16(sbase + ATT_QL + sofs, Ql + g);
    }

    auto load_kv = [&](int s, int k0) {
        const uint32_t st = sbase + ATT_STG0 + s * ATT_STG_BYTES;
#pragma unroll
        for (int t = 0; t < 2; t++) {
            int c = tid + t * 256;       // 0..511
            int row = c >> 3, ch = c & 7;
            size_t   g = (size_t)(k0 + row) * HDIM + ch * 8;
            uint32_t sofs = row * 128 + ((ch ^ (row & 7)) << 4);
            cp16(st + ATT_KH + sofs, Kh + g);
            cp16(st + ATT_KL + sofs, Kl + g);
            cp16(st + ATT_VH + sofs, Vh + g);
            cp16(st + ATT_VL + sofs, Vl + g);
        }
    };

    load_kv(0, 0);
    cp_commit();

    // ldmatrix address components
    const int a_r = w * 16 + (lane & 15);
    const int a_k = lane >> 4;
    const int a_x = a_r & 7;
    const int k_r = (lane & 7) + ((lane >> 4) << 3);     // + nf2*16
    const int k_k = (lane >> 3) & 1;
    const int v_r = (lane & 7) + (((lane >> 3) & 1) << 3);  // + kc*16
    const int v_c = lane >> 4;                               // + dg*2

    uint32_t qh[4][4], ql[4][4];

    float m_run[2] = {NEG_INF, NEG_INF};
    float l_run[2] = {0.0f, 0.0f};
    float acc_o[8][4];
#pragma unroll
    for (int i = 0; i < 8; i++)
#pragma unroll
        for (int j = 0; j < 4; j++) acc_o[i][j] = 0.0f;

    const int kmax = 2 * qb + 1;
    for (int kb = 0; kb <= kmax; kb++) {
        const int s  = kb & 1;
        const int k0 = kb * 64;
        if (kb + 1 <= kmax) {
            load_kv(s ^ 1, (kb + 1) * 64);
            cp_commit();
            cp_wait<1>();
        } else {
            cp_wait<0>();
        }
        __syncthreads();

        if (kb == 0) {
            // Q fragments -> registers (once)
#pragma unroll
            for (int ks = 0; ks < 4; ks++) {
                uint32_t off = a_r * 128 + ((((ks << 1) | a_k) ^ a_x) << 4);
                ldsm_x4(qh[ks], sbase + ATT_QH + off);
                ldsm_x4(ql[ks], sbase + ATT_QL + off);
            }
        }

        const uint32_t st = sbase + ATT_STG0 + s * ATT_STG_BYTES;

        // ---- S = Q K^T (16 x 64 per warp) ----
        float s_acc[8][4];
#pragma unroll
        for (int i = 0; i < 8; i++)
#pragma unroll
            for (int j = 0; j < 4; j++) s_acc[i][j] = 0.0f;

#pragma unroll
        for (int ks = 0; ks < 4; ks++) {
            uint32_t bh[4][4], bl[4][4];
#pragma unroll
            for (int nf2 = 0; nf2 < 4; nf2++) {
                int r = k_r + nf2 * 16;
                uint32_t off = r * 128 + ((((ks << 1) | k_k) ^ (r & 7)) << 4);
                ldsm_x4(bh[nf2], st + ATT_KH + off);
                ldsm_x4(bl[nf2], st + ATT_KL + off);
            }
#pragma unroll
            for (int nf = 0; nf < 8; nf++) {
                const uint32_t* bhp = &bh[nf >> 1][(nf & 1) * 2];
                const uint32_t* blp = &bl[nf >> 1][(nf & 1) * 2];
                mma_bf16(s_acc[nf], qh[ks], bhp);
                mma_bf16(s_acc[nf], ql[ks], bhp);
                mma_bf16(s_acc[nf], qh[ks], blp);
            }
        }

        // ---- causal mask (only possible on the last two tiles) ----
        if (kb >= 2 * qb) {
            const int qpos0 = q0 + w * 16 + (lane >> 2);
            const int kbase = k0 + (lane & 3) * 2;
#pragma unroll
            for (int nf = 0; nf < 8; nf++) {
                const int kp = kbase + nf * 8;
                if (kp     > qpos0)     s_acc[nf][0] = NEG_INF;
                if (kp + 1 > qpos0)     s_acc[nf][1] = NEG_INF;
                if (kp     > qpos0 + 8) s_acc[nf][2] = NEG_INF;
                if (kp + 1 > qpos0 + 8) s_acc[nf][3] = NEG_INF;
            }
        }

        // ---- online softmax (register-level, quad reduce) ----
#pragma unroll
        for (int half = 0; half < 2; half++) {
            float mx = NEG_INF;
#pragma unroll
            for (int nf = 0; nf < 8; nf++)
                mx = fmaxf(mx, fmaxf(s_acc[nf][half * 2], s_acc[nf][half * 2 + 1]));
            mx = fmaxf(mx, __shfl_xor_sync(0xffffffffu, mx, 1));
            mx = fmaxf(mx, __shfl_xor_sync(0xffffffffu, mx, 2));

            const float mnew  = fmaxf(m_run[half], mx);
            const float alpha = __expf(m_run[half] - mnew);
            m_run[half] = mnew;

            float sum = 0.0f;
#pragma unroll
            for (int nf = 0; nf < 8; nf++) {
                float p0 = __expf(s_acc[nf][half * 2]     - mnew);
                float p1 = __expf(s_acc[nf][half * 2 + 1] - mnew);
                s_acc[nf][half * 2]     = p0;
                s_acc[nf][half * 2 + 1] = p1;
                sum += p0 + p1;
            }
            sum += __shfl_xor_sync(0xffffffffu, sum, 1);
            sum += __shfl_xor_sync(0xffffffffu, sum, 2);
            l_run[half] = l_run[half] * alpha + sum;

#pragma unroll
            for (int dn = 0; dn < 8; dn++) {
                acc_o[dn][half * 2]     *= alpha;
                acc_o[dn][half * 2 + 1] *= alpha;
            }
        }

        // ---- O += P V  (P from registers, split hi/lo; V^T via ldmatrix.trans) ----
#pragma unroll
        for (int kc = 0; kc < 4; kc++) {
            uint32_t pah[4], pal[4];
#pragma unroll
            for (int q = 0; q < 2; q++) {          // nf = 2kc + q
                const float* sc = s_acc[2 * kc + q];
                float h0 = bfhi(sc[0]), h1 = bfhi(sc[1]);
                float h2 = bfhi(sc[2]), h3 = bfhi(sc[3]);
                pah[q * 2 + 0] = bf2pack(h0, h1);
                pah[q * 2 + 1] = bf2pack(h2, h3);
                pal[q * 2 + 0] = bf2pack(sc[0] - h0, sc[1] - h1);
                pal[q * 2 + 1] = bf2pack(sc[2] - h2, sc[3] - h3);
            }
            // A-frag order: a0,a1 = k-low half (nf 2kc), a2,a3 = k-high (nf 2kc+1)
            uint32_t ah[4] = {pah[0], pah[1], pah[2], pah[3]};
            uint32_t al[4] = {pal[0], pal[1], pal[2], pal[3]};
#pragma unroll
            for (int dg = 0; dg < 4; dg++) {
                int r = v_r + kc * 16;
                int ch = v_c + dg * 2;
                uint32_t off = r * 128 + ((ch ^ (r & 7)) << 4);
                uint32_t vh[4], vl[4];
                ldsm_x4_t(vh, st + ATT_VH + off);
                ldsm_x4_t(vl, st + ATT_VL + off);
#pragma unroll
                for (int q = 0; q < 2; q++) {
                    float* o = acc_o[dg * 2 + q];
                    mma_bf16(o, ah, &vh[q * 2]);
                    mma_bf16(o, al, &vh[q * 2]);
                    mma_bf16(o, ah, &vl[q * 2]);
                }
            }
        }
        __syncthreads();
    }

    // ---- epilogue: normalize, split, store token-major [MTOT][DIM] ----
    const float inv0 = 1.0f / l_run[0];
    const float inv1 = 1.0f / l_run[1];
    const int row0 = q0 + w * 16 + (lane >> 2);
    const size_t tok0 = (size_t)(b * SEQ + row0) * DIM + h * HDIM;
    const size_t tok1 = tok0 + 8 * DIM;
#pragma unroll
    for (int dn = 0; dn < 8; dn++) {
        const int d = dn * 8 + (lane & 3) * 2;
        float f0 = acc_o[dn][0] * inv0;
        float f1 = acc_o[dn][1] * inv0;
        float f2 = acc_o[dn][2] * inv1;
        float f3 = acc_o[dn][3] * inv1;
        unsigned short h0, l0, h1, l1, h2, l2, h3, l3;
        split1(f0, h0, l0); split1(f1, h1, l1);
        split1(f2, h2, l2); split1(f3, h3, l3);
        *(ushort2*)(g_o_hi + tok0 + d) = make_ushort2(h0, h1);
        *(ushort2*)(g_o_lo + tok0 + d) = make_ushort2(l0, l1);
        *(ushort2*)(g_o_hi + tok1 + d) = make_ushort2(h2, h3);
        *(ushort2*)(g_o_lo + tok1 + d) = make_ushort2(l2, l3);
    }
}

// ============================================================================
// launch
// ============================================================================
extern "C" void kernel_launch(void* const* d_in, const int* in_sizes, int n_in,
                              void* d_out, int out_size)
{
    const float* x  = (const float*)d_in[0];
    const float* Wq = (const float*)d_in[1];
    const float* Wk = (const float*)d_in[2];
    const float* Wv = (const float*)d_in[3];
    const float* Wo = (const float*)d_in[4];
    const float* bo = (const float*)d_in[5];
    float* out = (float*)d_out;

    cudaFuncSetAttribute(gemm_qkv_bf16,  cudaFuncAttributeMaxDynamicSharedMemorySize, GEMM_SMEM);
    cudaFuncSetAttribute(gemm_out_bf16,  cudaFuncAttributeMaxDynamicSharedMemorySize, GEMM_SMEM);
    cudaFuncSetAttribute(attn_mma_kernel, cudaFuncAttributeMaxDynamicSharedMemorySize, ATT_SMEM);

    // bf16 hi/lo splits of x and weights
    split_x_kernel<<<MTOT * DIM / 4 / 256, 256>>>(x);
    split_w_kernel<<<DIM * DIM / 4 / 256, 256>>>(Wq, 0);
    split_w_kernel<<<DIM * DIM / 4 / 256, 256>>>(Wk, 1);
    split_w_kernel<<<DIM * DIM / 4 / 256, 256>>>(Wv, 2);
    split_w_kernel<<<DIM * DIM / 4 / 256, 256>>>(Wo, 3);

    // QKV projections -> head-major bf16 hi/lo (Q pre-scaled)
    dim3 gridQKV(DIM / 64, MTOT / 128, 3);
    gemm_qkv_bf16<<<gridQKV, 256, GEMM_SMEM>>>();

    // tensor-core flash attention
    dim3 gridAtt(SEQ / 128, NHEADS, BATCH);
    attn_mma_kernel<<<gridAtt, 256, ATT_SMEM>>>();

    // output projection + bias
    dim3 gridOut(DIM / 64, MTOT / 128);
    gemm_out_bf16<<<gridOut, 256, GEMM_SMEM>>>(bo, out);
}